// round 2
// baseline (speedup 1.0000x reference)
#include <cuda_runtime.h>
#include <cstdint>
#include <cstddef>

// ============================================================================
// TT linear layer, rank-split two-GEMM formulation (no tcgen05: the harness
// builds through compute_103 virtual arch, which excludes sm_103a features).
//   y[b,(n1n2),(n3n4)] = sum_{r2,(m1m2)} L2[(n1n2),(r2,m1m2)] *
//                        sum_{(m3m4)}   R2[(r2,n3n4),(m3m4)] * x[b,(m1m2),(m3m4)]
// K1: T1[q][(b,m12)] = R2 . x^T          (M=1024, N=524288, K=64)
// K2: Yt[n34][b][n12] = T1-slice . L2^T  (M=8192, N=64, K=1024) x64 n34
// K3: transpose + bias -> y[b][n12][n34]
// All MMA operands rna-rounded to tf32; accumulation fp32.
// ============================================================================

__device__ __forceinline__ uint32_t smem_u32(const void* p) {
    uint32_t a;
    asm("{ .reg .u64 t; cvta.to.shared.u64 t, %1; cvt.u32.u64 %0, t; }" : "=r"(a) : "l"(p));
    return a;
}
__device__ __forceinline__ uint32_t f2tf32(float f) {
    uint32_t u;
    asm("cvt.rna.tf32.f32 %0, %1;" : "=r"(u) : "f"(f));
    return u;
}
__device__ __forceinline__ void cpa16(uint32_t d, const float* s) {
    asm volatile("cp.async.cg.shared.global [%0], [%1], 16;" :: "r"(d), "l"(s));
}
#define CP_COMMIT() asm volatile("cp.async.commit_group;" ::: "memory")
#define CP_WAIT1()  asm volatile("cp.async.wait_group 1;" ::: "memory")
#define CP_WAIT0()  asm volatile("cp.async.wait_group 0;" ::: "memory")

// D += A*B, m16n8k8 tf32 (fp32 accum)
#define MMA8(d, a, b) asm volatile( \
    "mma.sync.aligned.m16n8k8.row.col.f32.tf32.tf32.f32 " \
    "{%0,%1,%2,%3},{%4,%5,%6,%7},{%8,%9},{%0,%1,%2,%3};" \
    : "+f"((d)[0]), "+f"((d)[1]), "+f"((d)[2]), "+f"((d)[3]) \
    : "r"((a)[0]), "r"((a)[1]), "r"((a)[2]), "r"((a)[3]), "r"((b)[0]), "r"((b)[1]))

static constexpr int LDP = 68;          // padded SMEM row (floats): conflict-free frags
static constexpr int BM_TOT = 524288;   // 8192*64  (b,m12)

// ---------------- device scratch (statics: no cudaMalloc allowed) -----------
__device__ float g_R2[1024 * 64];                    // [q][m34], tf32-rounded
__device__ float g_L2[64 * 1024];                    // [n12][(r2,m12)], tf32-rounded
__device__ float g_T1a[(size_t)512 * BM_TOT];        // T1 rows q = 0..511   (1 GiB)
__device__ float g_T1b[(size_t)512 * BM_TOT];        // T1 rows q = 512..1023(1 GiB)
__device__ float g_Yt[(size_t)64 * 8192 * 64];       // [n34][b][n12] (128 MB)

// ---------------- prep: build R2 and L2 from TT cores ----------------------
__global__ void k_r2(const float* __restrict__ c2, const float* __restrict__ c3) {
    int t = blockIdx.x * 256 + threadIdx.x;          // 65536
    int m34 = t & 63, q = t >> 6;
    int m3 = m34 >> 3, m4 = m34 & 7;
    int r2 = q >> 6, n3 = (q >> 3) & 7, n4 = q & 7;
    float s = 0.f;
#pragma unroll
    for (int r3 = 0; r3 < 16; r3++)
        s += c2[((r2 * 8 + n3) * 8 + m3) * 16 + r3] * c3[(r3 * 8 + n4) * 8 + m4];
    g_R2[t] = __uint_as_float(f2tf32(s));
}

__global__ void k_l2(const float* __restrict__ c0, const float* __restrict__ c1) {
    int t = blockIdx.x * 256 + threadIdx.x;          // 65536
    int kk = t & 1023, n12 = t >> 10;
    int r2 = kk >> 6, m1 = (kk >> 3) & 7, m2 = kk & 7;
    int n1 = n12 >> 3, n2 = n12 & 7;
    float s = 0.f;
#pragma unroll
    for (int r1 = 0; r1 < 16; r1++)
        s += c0[(n1 * 8 + m1) * 16 + r1] * c1[((r1 * 8 + n2) * 8 + m2) * 16 + r2];
    g_L2[t] = __uint_as_float(f2tf32(s));
}

// ---------------- K1: T1[q][(b,m12)] = R2 . x^T  (tile 128x128, K=64) -------
__global__ void __launch_bounds__(256) k_gemm1(const float* __restrict__ x) {
    extern __shared__ float sm[];
    const int tid = threadIdx.x;
    const int bm0 = blockIdx.x * 128;
    const int qt  = blockIdx.y;                      // 0..7
    float* sA = sm;                                  // 128 x LDP  (R2 q-tile)
    float* sB = sm + 128 * LDP;                      // 128 x LDP  (x bm-tile)
    const uint32_t sAu = smem_u32(sA), sBu = smem_u32(sB);

    const float* gA = g_R2 + (size_t)qt * 128 * 64;  // contiguous 32KB
    const float* gB = x + (size_t)bm0 * 64;          // contiguous 32KB
#pragma unroll
    for (int j = 0; j < 8; j++) {
        int i = tid + j * 256;                       // 0..2047 (float4 units)
        int r = i >> 4, cc = i & 15;
        uint32_t doff = (uint32_t)(r * LDP + cc * 4) * 4u;
        cpa16(sAu + doff, gA + i * 4);
        cpa16(sBu + doff, gB + i * 4);
    }
    CP_COMMIT(); CP_WAIT0();
    __syncthreads();

    const int wid = tid >> 5, lane = tid & 31;
    const int wm = wid & 3, wn = wid >> 2;           // 4 x 2 warps, warp 32x64
    const int g = lane >> 2, t4 = lane & 3;

    float acc[2][8][4];
#pragma unroll
    for (int a = 0; a < 2; a++)
#pragma unroll
        for (int b = 0; b < 8; b++)
#pragma unroll
            for (int d = 0; d < 4; d++) acc[a][b][d] = 0.f;

#pragma unroll
    for (int s = 0; s < 8; s++) {
        const int k = s * 8;
        uint32_t af[2][4], bf[8][2];
#pragma unroll
        for (int mf = 0; mf < 2; mf++) {
            int r = wm * 32 + mf * 16 + g;
            af[mf][0] = __float_as_uint(sA[r * LDP + k + t4]);        // R2 pre-rounded
            af[mf][1] = __float_as_uint(sA[(r + 8) * LDP + k + t4]);
            af[mf][2] = __float_as_uint(sA[r * LDP + k + t4 + 4]);
            af[mf][3] = __float_as_uint(sA[(r + 8) * LDP + k + t4 + 4]);
        }
#pragma unroll
        for (int nf = 0; nf < 8; nf++) {
            int cn = wn * 64 + nf * 8 + g;
            bf[nf][0] = f2tf32(sB[cn * LDP + k + t4]);                // x: round here
            bf[nf][1] = f2tf32(sB[cn * LDP + k + t4 + 4]);
        }
#pragma unroll
        for (int mf = 0; mf < 2; mf++)
#pragma unroll
            for (int nf = 0; nf < 8; nf++)
                MMA8(acc[mf][nf], af[mf], bf[nf]);
    }

    // store tf32-rounded T1 (so K2's A needs no conversion)
    float* base = (qt < 4) ? g_T1a : g_T1b;
    const int ql0 = (qt & 3) * 128;
#pragma unroll
    for (int mf = 0; mf < 2; mf++) {
        int r0 = wm * 32 + mf * 16 + g;
#pragma unroll
        for (int nf = 0; nf < 8; nf++) {
            int col = bm0 + wn * 64 + nf * 8 + t4 * 2;
            float2 v0, v1;
            v0.x = __uint_as_float(f2tf32(acc[mf][nf][0]));
            v0.y = __uint_as_float(f2tf32(acc[mf][nf][1]));
            v1.x = __uint_as_float(f2tf32(acc[mf][nf][2]));
            v1.y = __uint_as_float(f2tf32(acc[mf][nf][3]));
            *reinterpret_cast<float2*>(base + ((size_t)(ql0 + r0) << 19) + col) = v0;
            *reinterpret_cast<float2*>(base + ((size_t)(ql0 + r0 + 8) << 19) + col) = v1;
        }
    }
}

// ---------------- K2: Yt[n34][b][n12] = T1 . L2^T  (tile 128x64, K=1024) ----
__device__ __forceinline__ void k2_load(int tid, uint32_t sa, uint32_t sb,
                                        int bt, int n34, int r2) {
    const float* base = (r2 < 8) ? g_T1a : g_T1b;
    const float* gA = base + ((size_t)((r2 & 7) * 64 + n34) << 19) + (size_t)bt * 8192;
#pragma unroll
    for (int j = 0; j < 8; j++) {
        int i = tid + j * 256;                       // A: 128 rows x 16 float4
        int r = i >> 4, cc = i & 15;
        cpa16(sa + (uint32_t)(r * LDP + cc * 4) * 4u, gA + i * 4);
    }
#pragma unroll
    for (int j = 0; j < 4; j++) {
        int i = tid + j * 256;                       // B: 64 rows x 16 float4
        int r = i >> 4, cc = i & 15;
        cpa16(sb + (uint32_t)(r * LDP + cc * 4) * 4u,
              g_L2 + r * 1024 + r2 * 64 + cc * 4);
    }
}

__global__ void __launch_bounds__(256) k_gemm2() {
    extern __shared__ float sm[];
    const int tid = threadIdx.x;
    const int bt  = blockIdx.x;                      // 0..63 (128 b's each)
    const int n34 = blockIdx.y;                      // 0..63
    const int BUFSZ = (128 + 64) * LDP;
    const uint32_t s0 = smem_u32(sm);

    k2_load(tid, s0, s0 + (uint32_t)(128 * LDP) * 4u, bt, n34, 0);
    CP_COMMIT();

    const int wid = tid >> 5, lane = tid & 31;
    const int wm = wid & 3, wn = wid >> 2;           // 4 x 2 warps, warp 32x32
    const int g = lane >> 2, t4 = lane & 3;

    float acc[2][4][4];
#pragma unroll
    for (int a = 0; a < 2; a++)
#pragma unroll
        for (int b = 0; b < 4; b++)
#pragma unroll
            for (int d = 0; d < 4; d++) acc[a][b][d] = 0.f;

    for (int r2 = 0; r2 < 16; r2++) {
        const int buf = r2 & 1;
        if (r2 < 15) {
            uint32_t sa = s0 + (uint32_t)((buf ^ 1) * BUFSZ) * 4u;
            k2_load(tid, sa, sa + (uint32_t)(128 * LDP) * 4u, bt, n34, r2 + 1);
            CP_COMMIT(); CP_WAIT1();
        } else {
            CP_WAIT0();
        }
        __syncthreads();
        const float* sA = sm + buf * BUFSZ;
        const float* sB = sA + 128 * LDP;
#pragma unroll
        for (int s = 0; s < 8; s++) {
            const int k = s * 8;
            uint32_t af[2][4], bf[4][2];
#pragma unroll
            for (int mf = 0; mf < 2; mf++) {
                int r = wm * 32 + mf * 16 + g;
                af[mf][0] = __float_as_uint(sA[r * LDP + k + t4]);
                af[mf][1] = __float_as_uint(sA[(r + 8) * LDP + k + t4]);
                af[mf][2] = __float_as_uint(sA[r * LDP + k + t4 + 4]);
                af[mf][3] = __float_as_uint(sA[(r + 8) * LDP + k + t4 + 4]);
            }
#pragma unroll
            for (int nf = 0; nf < 4; nf++) {
                int cn = wn * 32 + nf * 8 + g;
                bf[nf][0] = __float_as_uint(sB[cn * LDP + k + t4]);
                bf[nf][1] = __float_as_uint(sB[cn * LDP + k + t4 + 4]);
            }
#pragma unroll
            for (int mf = 0; mf < 2; mf++)
#pragma unroll
                for (int nf = 0; nf < 4; nf++)
                    MMA8(acc[mf][nf], af[mf], bf[nf]);
        }
        __syncthreads();
    }

    // epilogue -> Yt[n34][bt*128+row][n12]
    float* yt = g_Yt + ((size_t)n34 * 8192 + (size_t)bt * 128) * 64;
#pragma unroll
    for (int mf = 0; mf < 2; mf++) {
        int r0 = wm * 32 + mf * 16 + g;
#pragma unroll
        for (int nf = 0; nf < 4; nf++) {
            int col = wn * 32 + nf * 8 + t4 * 2;
            float2 v0, v1;
            v0.x = acc[mf][nf][0]; v0.y = acc[mf][nf][1];
            v1.x = acc[mf][nf][2]; v1.y = acc[mf][nf][3];
            *reinterpret_cast<float2*>(yt + (size_t)r0 * 64 + col) = v0;
            *reinterpret_cast<float2*>(yt + (size_t)(r0 + 8) * 64 + col) = v1;
        }
    }
}

// ---------------- K3: y[b][n12][n34] = Yt[n34][b][n12] + bias ---------------
__global__ void __launch_bounds__(256) k_tr(const float* __restrict__ bias,
                                            float* __restrict__ y) {
    extern __shared__ float sm[];                    // s[(b*64+n12)*65 + n34]
    const int tid = threadIdx.x;
    const int b0 = blockIdx.x * 8;
#pragma unroll
    for (int j = 0; j < 32; j++) {
        int e = tid + j * 256;                       // 0..8191 float4 units
        int n12c = e & 15, b = (e >> 4) & 7, n34 = e >> 7;
        float4 v = *reinterpret_cast<const float4*>(
            g_Yt + ((size_t)n34 * 8192 + b0 + b) * 64 + n12c * 4);
        int rb = (b * 64 + n12c * 4) * 65 + n34;
        sm[rb] = v.x; sm[rb + 65] = v.y; sm[rb + 130] = v.z; sm[rb + 195] = v.w;
    }
    __syncthreads();
#pragma unroll
    for (int j = 0; j < 32; j++) {
        int e = tid + j * 256;
        int n34c = e & 15, n12 = (e >> 4) & 63, b = e >> 10;
        int sb = (b * 64 + n12) * 65 + n34c * 4;
        float4 bv = *reinterpret_cast<const float4*>(bias + n12 * 64 + n34c * 4);
        float4 o;
        o.x = sm[sb]     + bv.x;
        o.y = sm[sb + 1] + bv.y;
        o.z = sm[sb + 2] + bv.z;
        o.w = sm[sb + 3] + bv.w;
        *reinterpret_cast<float4*>(y + (size_t)(b0 + b) * 4096 + n12 * 64 + n34c * 4) = o;
    }
}

// ---------------- launch ----------------------------------------------------
extern "C" void kernel_launch(void* const* d_in, const int* in_sizes, int n_in,
                              void* d_out, int out_size) {
    const float* x    = (const float*)d_in[0];
    const float* c0   = (const float*)d_in[1];
    const float* c1   = (const float*)d_in[2];
    const float* c2   = (const float*)d_in[3];
    const float* c3   = (const float*)d_in[4];
    const float* bias = (const float*)d_in[5];
    float* out = (float*)d_out;

    cudaFuncSetAttribute(k_gemm1, cudaFuncAttributeMaxDynamicSharedMemorySize, 2 * 128 * LDP * 4);
    cudaFuncSetAttribute(k_gemm2, cudaFuncAttributeMaxDynamicSharedMemorySize, 2 * (128 + 64) * LDP * 4);
    cudaFuncSetAttribute(k_tr,    cudaFuncAttributeMaxDynamicSharedMemorySize, 8 * 64 * 65 * 4);

    k_r2<<<256, 256>>>(c2, c3);
    k_l2<<<256, 256>>>(c0, c1);
    k_gemm1<<<dim3(4096, 8), 256, 2 * 128 * LDP * 4>>>(x);
    k_gemm2<<<dim3(64, 64), 256, 2 * (128 + 64) * LDP * 4>>>();
    k_tr<<<1024, 256, 8 * 64 * 65 * 4>>>(bias, out);
}

// round 3
// speedup vs baseline: 3.0229x; 3.0229x over previous
#include <cuda_runtime.h>
#include <cuda_fp16.h>
#include <cstdint>
#include <cstddef>

// ============================================================================
// TT linear layer, fully fused Kronecker-sandwich form:
//   Y_b = sum_{r2=0..15}  L2_r2 (64x64) . X_b (64x64) . R2_r2^T (64x64)
// where X_b = x[b] viewed as [m12][m34],  Y_b = y[b] as [n12][n34].
// One CTA = 4 batch samples. The r2 intermediate Zt (64x256 fp16) stays in
// SMEM; HBM traffic is just x once in, y once out (~290 MB total).
// fp16 operands (same mantissa as tf32), fp32 accumulation in registers.
//
// GEMM1 (per r2): Zt[n34][(b,m12)] = R2_r2[n34][m34] . X[(b,m12)][m34]^T
//                 M=64, N=256, K=64   (A,B both natural row-major [.][K])
// GEMM2 (per r2): Y[(b)][n12][n34] += L2_r2[n12][m12] . Zt[n34][b*64+m12]^T
//                 per b: M=64, N=64, K=64
// ============================================================================

__device__ __forceinline__ uint32_t smem_u32(const void* p) {
    uint32_t a;
    asm("{ .reg .u64 t; cvta.to.shared.u64 t, %1; cvt.u32.u64 %0, t; }" : "=r"(a) : "l"(p));
    return a;
}
__device__ __forceinline__ void cpa16(uint32_t d, const void* s) {
    asm volatile("cp.async.cg.shared.global [%0], [%1], 16;" :: "r"(d), "l"(s));
}
#define CP_COMMIT() asm volatile("cp.async.commit_group;" ::: "memory")
#define CP_WAIT0()  asm volatile("cp.async.wait_group 0;" ::: "memory")

// D += A*B : m16n8k16, fp16 inputs, fp32 accum
#define MMA16(d, a, b) asm volatile( \
    "mma.sync.aligned.m16n8k16.row.col.f32.f16.f16.f32 " \
    "{%0,%1,%2,%3},{%4,%5,%6,%7},{%8,%9},{%0,%1,%2,%3};" \
    : "+f"((d)[0]), "+f"((d)[1]), "+f"((d)[2]), "+f"((d)[3]) \
    : "r"((a)[0]), "r"((a)[1]), "r"((a)[2]), "r"((a)[3]), "r"((b)[0]), "r"((b)[1]))

// ---------------- layout constants (fp16 element units) --------------------
static constexpr int LDX = 72;    // X rows [256][64] padded
static constexpr int LDZ = 264;   // Zt rows [64][256] padded
static constexpr int LDR = 72;    // R2/L2 slices [64][64] padded

static constexpr int OFF_X  = 0;                   // 256*72          = 18432
static constexpr int OFF_Z  = 18432;               // 64*264          = 16896
static constexpr int OFF_R0 = OFF_Z  + 16896;      // 35328
static constexpr int OFF_R1 = OFF_R0 + 64 * LDR;   // 39936
static constexpr int OFF_L0 = OFF_R1 + 64 * LDR;   // 44544
static constexpr int OFF_L1 = OFF_L0 + 64 * LDR;   // 49152
static constexpr int SMEM_HALFS = OFF_L1 + 64 * LDR;           // 53760
static constexpr uint32_t SMEM_BYTES = SMEM_HALFS * 2;         // 107520

// ---------------- device-side factor slices (no cudaMalloc allowed) --------
__device__ __half g_R2h[16 * 64 * 64];   // [r2][n34][m34]
__device__ __half g_L2h[16 * 64 * 64];   // [r2][n12][m12]

// ---------------- prep: contract (c2,c3) -> R2, (c0,c1) -> L2 --------------
__global__ void k_r2h(const float* __restrict__ c2, const float* __restrict__ c3) {
    int t = blockIdx.x * 256 + threadIdx.x;          // 65536
    int m34 = t & 63, n34 = (t >> 6) & 63, r2 = t >> 12;
    int m3 = m34 >> 3, m4 = m34 & 7, n3 = n34 >> 3, n4 = n34 & 7;
    float s = 0.f;
#pragma unroll
    for (int r3 = 0; r3 < 16; r3++)
        s += c2[((r2 * 8 + n3) * 8 + m3) * 16 + r3] * c3[(r3 * 8 + n4) * 8 + m4];
    g_R2h[t] = __float2half_rn(s);
}
__global__ void k_l2h(const float* __restrict__ c0, const float* __restrict__ c1) {
    int t = blockIdx.x * 256 + threadIdx.x;          // 65536
    int m12 = t & 63, n12 = (t >> 6) & 63, r2 = t >> 12;
    int m1 = m12 >> 3, m2 = m12 & 7, n1 = n12 >> 3, n2 = n12 & 7;
    float s = 0.f;
#pragma unroll
    for (int r1 = 0; r1 < 16; r1++)
        s += c0[(n1 * 8 + m1) * 16 + r1] * c1[((r1 * 8 + n2) * 8 + m2) * 16 + r2];
    g_L2h[t] = __float2half_rn(s);
}

// ---------------- fused main kernel -----------------------------------------
__global__ void __launch_bounds__(256, 1)
tt_fused(const float* __restrict__ x, const float* __restrict__ bias,
         float* __restrict__ y) {
    extern __shared__ __half sm[];
    const uint32_t sb = smem_u32(sm);
    const int tid = threadIdx.x, wid = tid >> 5, lane = tid & 31;
    const int g = lane >> 2, t4 = lane & 3;
    const int b0 = blockIdx.x * 4;

    __half* sX = sm + OFF_X;
    __half* sZ = sm + OFF_Z;
    const int R_OFF[2] = {OFF_R0, OFF_R1};
    const int L_OFF[2] = {OFF_L0, OFF_L1};

    // ---- load X (4 samples x 4096 fp32) -> fp16 SMEM [ (b,m12) ][ m34 ] ----
    const float4* gx = reinterpret_cast<const float4*>(x + (size_t)b0 * 4096);
#pragma unroll
    for (int j = 0; j < 16; j++) {
        int i = tid + j * 256;            // 0..4095 float4 units
        int row = i >> 4, c = i & 15;
        float4 v = gx[i];
        *reinterpret_cast<__half2*>(sX + row * LDX + c * 4)     = __floats2half2_rn(v.x, v.y);
        *reinterpret_cast<__half2*>(sX + row * LDX + c * 4 + 2) = __floats2half2_rn(v.z, v.w);
    }

    // ---- prefetch factor slices for r2 = 0 ----
#pragma unroll
    for (int k = 0; k < 2; k++) {
        int i = tid + k * 256;            // 0..511 (16B chunks)
        int row = i >> 3, c = i & 7;
        cpa16(sb + (uint32_t)(OFF_R0 + row * LDR + c * 8) * 2u, g_R2h + row * 64 + c * 8);
        cpa16(sb + (uint32_t)(OFF_L0 + row * LDR + c * 8) * 2u, g_L2h + row * 64 + c * 8);
    }
    CP_COMMIT();

    float accY[4][4][4];
#pragma unroll
    for (int a = 0; a < 4; a++)
#pragma unroll
        for (int b = 0; b < 4; b++)
#pragma unroll
            for (int d = 0; d < 4; d++) accY[a][b][d] = 0.f;

    const int n1base = wid * 32;                      // GEMM1: warp's N-range
    const int bb = wid >> 1, n2base = (wid & 1) * 32; // GEMM2: warp's (b, n34)

    for (int r2 = 0; r2 < 16; r2++) {
        const int buf = r2 & 1;
        CP_WAIT0();
        __syncthreads();   // factors ready; prev GEMM2 done reading sZ & old buf

        // prefetch next r2's factors into the other buffer
        if (r2 < 15) {
            const __half* gR = g_R2h + (r2 + 1) * 4096;
            const __half* gL = g_L2h + (r2 + 1) * 4096;
            const uint32_t dR = sb + (uint32_t)R_OFF[buf ^ 1] * 2u;
            const uint32_t dL = sb + (uint32_t)L_OFF[buf ^ 1] * 2u;
#pragma unroll
            for (int k = 0; k < 2; k++) {
                int i = tid + k * 256;
                int row = i >> 3, c = i & 7;
                cpa16(dR + (uint32_t)(row * LDR + c * 8) * 2u, gR + row * 64 + c * 8);
                cpa16(dL + (uint32_t)(row * LDR + c * 8) * 2u, gL + row * 64 + c * 8);
            }
            CP_COMMIT();
        }

        // ---- GEMM1: Zt[n34][(b,m12)] = R2_r2 . X^T   (M=64, N=256, K=64) ----
        const __half* sR = sm + R_OFF[buf];
        float z[4][4][4];
#pragma unroll
        for (int a = 0; a < 4; a++)
#pragma unroll
            for (int b = 0; b < 4; b++)
#pragma unroll
                for (int d = 0; d < 4; d++) z[a][b][d] = 0.f;

#pragma unroll
        for (int ks = 0; ks < 4; ks++) {
            uint32_t afr[4][4];
#pragma unroll
            for (int mt = 0; mt < 4; mt++) {
                const __half* ap = sR + (mt * 16 + g) * LDR + ks * 16 + t4 * 2;
                afr[mt][0] = *reinterpret_cast<const uint32_t*>(ap);
                afr[mt][1] = *reinterpret_cast<const uint32_t*>(ap + 8 * LDR);
                afr[mt][2] = *reinterpret_cast<const uint32_t*>(ap + 8);
                afr[mt][3] = *reinterpret_cast<const uint32_t*>(ap + 8 * LDR + 8);
            }
#pragma unroll
            for (int nt = 0; nt < 4; nt++) {
                const __half* bp = sX + (n1base + nt * 8 + g) * LDX + ks * 16 + t4 * 2;
                uint32_t bfr[2] = { *reinterpret_cast<const uint32_t*>(bp),
                                    *reinterpret_cast<const uint32_t*>(bp + 8) };
#pragma unroll
                for (int mt = 0; mt < 4; mt++) MMA16(z[mt][nt], afr[mt], bfr);
            }
        }
        // store Zt tile (warp owns cols n1base..n1base+31), fp16
#pragma unroll
        for (int mt = 0; mt < 4; mt++)
#pragma unroll
            for (int nt = 0; nt < 4; nt++) {
                int col = n1base + nt * 8 + t4 * 2;
                *reinterpret_cast<__half2*>(sZ + (mt * 16 + g) * LDZ + col) =
                    __floats2half2_rn(z[mt][nt][0], z[mt][nt][1]);
                *reinterpret_cast<__half2*>(sZ + (mt * 16 + g + 8) * LDZ + col) =
                    __floats2half2_rn(z[mt][nt][2], z[mt][nt][3]);
            }
        __syncthreads();

        // ---- GEMM2: Y_b[n12][n34] += L2_r2 . Zt_b^T  (per warp: b=wid>>1) ----
        const __half* sL = sm + L_OFF[buf];
#pragma unroll
        for (int ks = 0; ks < 4; ks++) {
            uint32_t afr[4][4];
#pragma unroll
            for (int mt = 0; mt < 4; mt++) {
                const __half* ap = sL + (mt * 16 + g) * LDR + ks * 16 + t4 * 2;
                afr[mt][0] = *reinterpret_cast<const uint32_t*>(ap);
                afr[mt][1] = *reinterpret_cast<const uint32_t*>(ap + 8 * LDR);
                afr[mt][2] = *reinterpret_cast<const uint32_t*>(ap + 8);
                afr[mt][3] = *reinterpret_cast<const uint32_t*>(ap + 8 * LDR + 8);
            }
#pragma unroll
            for (int nt = 0; nt < 4; nt++) {
                const __half* bp = sZ + (n2base + nt * 8 + g) * LDZ + bb * 64 + ks * 16 + t4 * 2;
                uint32_t bfr[2] = { *reinterpret_cast<const uint32_t*>(bp),
                                    *reinterpret_cast<const uint32_t*>(bp + 8) };
#pragma unroll
                for (int mt = 0; mt < 4; mt++) MMA16(accY[mt][nt], afr[mt], bfr);
            }
        }
    }

    // ---- epilogue: Y + bias -> y[b0+bb][n12*64+n34], warp tile [64][32] ----
    float* yb = y + (size_t)(b0 + bb) * 4096;
#pragma unroll
    for (int mt = 0; mt < 4; mt++)
#pragma unroll
        for (int nt = 0; nt < 4; nt++) {
            int row = mt * 16 + g;
            int col = n2base + nt * 8 + t4 * 2;
            float2 bv0 = *reinterpret_cast<const float2*>(bias + row * 64 + col);
            float2 bv1 = *reinterpret_cast<const float2*>(bias + (row + 8) * 64 + col);
            float2 o0, o1;
            o0.x = accY[mt][nt][0] + bv0.x;  o0.y = accY[mt][nt][1] + bv0.y;
            o1.x = accY[mt][nt][2] + bv1.x;  o1.y = accY[mt][nt][3] + bv1.y;
            *reinterpret_cast<float2*>(yb + row * 64 + col) = o0;
            *reinterpret_cast<float2*>(yb + (row + 8) * 64 + col) = o1;
        }
}

// ---------------- launch -----------------------------------------------------
extern "C" void kernel_launch(void* const* d_in, const int* in_sizes, int n_in,
                              void* d_out, int out_size) {
    const float* x    = (const float*)d_in[0];
    const float* c0   = (const float*)d_in[1];
    const float* c1   = (const float*)d_in[2];
    const float* c2   = (const float*)d_in[3];
    const float* c3   = (const float*)d_in[4];
    const float* bias = (const float*)d_in[5];
    float* out = (float*)d_out;

    k_r2h<<<256, 256>>>(c2, c3);
    k_l2h<<<256, 256>>>(c0, c1);

    cudaFuncSetAttribute(tt_fused, cudaFuncAttributeMaxDynamicSharedMemorySize, SMEM_BYTES);
    tt_fused<<<2048, 256, SMEM_BYTES>>>(x, bias, out);
}

// round 4
// speedup vs baseline: 3.7616x; 1.2444x over previous
#include <cuda_runtime.h>
#include <cuda_fp16.h>
#include <cstdint>
#include <cstddef>

// ============================================================================
// TT linear layer, fused Kronecker-sandwich:
//   Y_b = sum_{r2=0..15}  L2_r2 (64x64) . X_b (64x64) . R2_r2^T (64x64)
// CTA = 4 samples, 256 threads. r2 intermediate Zt double-buffered in SMEM.
// ldmatrix fragment loads, cp.async 4-deep factor ring (prefetch 2 ahead),
// ONE __syncthreads per r2 iteration. fp16 operands, fp32 accumulation.
// ============================================================================

__device__ __forceinline__ uint32_t smem_u32(const void* p) {
    uint32_t a;
    asm("{ .reg .u64 t; cvta.to.shared.u64 t, %1; cvt.u32.u64 %0, t; }" : "=r"(a) : "l"(p));
    return a;
}
__device__ __forceinline__ void cpa16(uint32_t d, const void* s) {
    asm volatile("cp.async.cg.shared.global [%0], [%1], 16;" :: "r"(d), "l"(s));
}
#define CP_COMMIT() asm volatile("cp.async.commit_group;" ::: "memory")
#define CP_WAIT1()  asm volatile("cp.async.wait_group 1;" ::: "memory")
#define CP_WAIT0()  asm volatile("cp.async.wait_group 0;" ::: "memory")

// D += A*B : m16n8k16, fp16 inputs, fp32 accum
#define MMA16(d, a0, a1, a2, a3, b0, b1) asm volatile( \
    "mma.sync.aligned.m16n8k16.row.col.f32.f16.f16.f32 " \
    "{%0,%1,%2,%3},{%4,%5,%6,%7},{%8,%9},{%0,%1,%2,%3};" \
    : "+f"((d)[0]), "+f"((d)[1]), "+f"((d)[2]), "+f"((d)[3]) \
    : "r"(a0), "r"(a1), "r"(a2), "r"(a3), "r"(b0), "r"(b1))

#define LDSM4(r0, r1, r2_, r3, addr) asm volatile( \
    "ldmatrix.sync.aligned.m8n8.x4.shared.b16 {%0,%1,%2,%3}, [%4];" \
    : "=r"(r0), "=r"(r1), "=r"(r2_), "=r"(r3) : "r"(addr))

// ---------------- layout constants (fp16 element units) --------------------
static constexpr int LDX = 72;    // X   [256][64]  pad: 144B row ≡ 16 mod 128
static constexpr int LDZ = 264;   // Zt  [64][256]  pad: 528B row ≡ 16 mod 128
static constexpr int LDR = 72;    // R/L [64][64]

static constexpr int OFF_X  = 0;                         // 256*72 = 18432
static constexpr int OFF_Z0 = 18432;                     // 64*264 = 16896
static constexpr int OFF_Z1 = OFF_Z0 + 64 * LDZ;         // 35328
static constexpr int OFF_F  = OFF_Z1 + 64 * LDZ;         // 52224
static constexpr int FBUF   = 2 * 64 * LDR;              // 9216 halves (R then L)
static constexpr int SMEM_HALFS = OFF_F + 4 * FBUF;      // 89088
static constexpr uint32_t SMEM_BYTES = SMEM_HALFS * 2;   // 178176

// ---------------- device-side factor slices --------------------------------
__device__ __half g_R2h[16 * 64 * 64];   // [r2][n34][m34]
__device__ __half g_L2h[16 * 64 * 64];   // [r2][n12][m12]

// ---------------- prep: contract (c2,c3) -> R2, (c0,c1) -> L2 --------------
__global__ void k_r2h(const float* __restrict__ c2, const float* __restrict__ c3) {
    int t = blockIdx.x * 256 + threadIdx.x;
    int m34 = t & 63, n34 = (t >> 6) & 63, r2 = t >> 12;
    int m3 = m34 >> 3, m4 = m34 & 7, n3 = n34 >> 3, n4 = n34 & 7;
    float s = 0.f;
#pragma unroll
    for (int r3 = 0; r3 < 16; r3++)
        s += c2[((r2 * 8 + n3) * 8 + m3) * 16 + r3] * c3[(r3 * 8 + n4) * 8 + m4];
    g_R2h[t] = __float2half_rn(s);
}
__global__ void k_l2h(const float* __restrict__ c0, const float* __restrict__ c1) {
    int t = blockIdx.x * 256 + threadIdx.x;
    int m12 = t & 63, n12 = (t >> 6) & 63, r2 = t >> 12;
    int m1 = m12 >> 3, m2 = m12 & 7, n1 = n12 >> 3, n2 = n12 & 7;
    float s = 0.f;
#pragma unroll
    for (int r1 = 0; r1 < 16; r1++)
        s += c0[(n1 * 8 + m1) * 16 + r1] * c1[((r1 * 8 + n2) * 8 + m2) * 16 + r2];
    g_L2h[t] = __float2half_rn(s);
}

// ---------------- factor prefetch: R2[r2] + L2[r2] -> fbuf slot -------------
__device__ __forceinline__ void prefetch_factors(uint32_t sb, int tid, int r2) {
    const uint32_t f0 = sb + (uint32_t)(OFF_F + (r2 & 3) * FBUF) * 2u;
    const __half* gR = g_R2h + r2 * 4096;
    const __half* gL = g_L2h + r2 * 4096;
#pragma unroll
    for (int k = 0; k < 2; k++) {
        int i = tid + k * 256;            // 0..511 16B chunks
        int row = i >> 3, c = i & 7;
        uint32_t d = (uint32_t)(row * LDR + c * 8) * 2u;
        cpa16(f0 + d, gR + row * 64 + c * 8);
        cpa16(f0 + (uint32_t)(64 * LDR) * 2u + d, gL + row * 64 + c * 8);
    }
    CP_COMMIT();
}

// ---------------- fused main kernel -----------------------------------------
__global__ void __launch_bounds__(256, 1)
tt_fused(const float* __restrict__ x, const float* __restrict__ bias,
         float* __restrict__ y) {
    extern __shared__ __half sm[];
    const uint32_t sb = smem_u32(sm);
    const int tid = threadIdx.x, wid = tid >> 5, lane = tid & 31;
    const int g = lane >> 2, t4 = lane & 3;
    const int b0 = blockIdx.x * 4;

    // ldmatrix per-thread selectors
    const int aRow = lane & 15,                  aCol = (lane >> 4) * 8;     // A x4 (16x16)
    const int bRow = ((lane >> 4) * 8) + (lane & 7), bCol = ((lane >> 3) & 1) * 8; // B x4 (2 nt)

    const int n1base = wid * 32;                       // GEMM1 N-range
    const int bb = wid >> 1, n2base = (wid & 1) * 32;  // GEMM2 (sample, n34-range)

    // ---- load X (4 samples x 4096 fp32) -> fp16 SMEM [(b,m12)][m34] --------
    {
        const float4* gx = reinterpret_cast<const float4*>(x + (size_t)b0 * 4096);
        __half* sX = sm + OFF_X;
#pragma unroll
        for (int j = 0; j < 16; j++) {
            int i = tid + j * 256;
            int row = i >> 4, c = i & 15;
            float4 v = gx[i];
            *reinterpret_cast<__half2*>(sX + row * LDX + c * 4)     = __floats2half2_rn(v.x, v.y);
            *reinterpret_cast<__half2*>(sX + row * LDX + c * 4 + 2) = __floats2half2_rn(v.z, v.w);
        }
    }

    prefetch_factors(sb, tid, 0);
    prefetch_factors(sb, tid, 1);
    CP_WAIT1();                // F(0) complete, F(1) in flight
    __syncthreads();           // publish X and F(0)

    float accY[4][4][4];
#pragma unroll
    for (int a = 0; a < 4; a++)
#pragma unroll
        for (int b = 0; b < 4; b++)
#pragma unroll
            for (int d = 0; d < 4; d++) accY[a][b][d] = 0.f;

#pragma unroll 1
    for (int i = 0; i < 16; i++) {
        if (i + 2 < 16) prefetch_factors(sb, tid, i + 2);

        const uint32_t fR = sb + (uint32_t)(OFF_F + (i & 3) * FBUF) * 2u;
        const uint32_t fL = fR + (uint32_t)(64 * LDR) * 2u;
        const uint32_t zOff = (i & 1) ? OFF_Z1 : OFF_Z0;
        __half* sZ = sm + zOff;

        // ---- GEMM1: Zt[n34][(b,m12)] = R2_r2 . X^T (M=64,N=256 shard,K=64) --
        float z[4][4][4];
#pragma unroll
        for (int a = 0; a < 4; a++)
#pragma unroll
            for (int b = 0; b < 4; b++)
#pragma unroll
                for (int d = 0; d < 4; d++) z[a][b][d] = 0.f;

#pragma unroll
        for (int ks = 0; ks < 4; ks++) {
            uint32_t af[4][4];
#pragma unroll
            for (int mt = 0; mt < 4; mt++) {
                uint32_t addr = fR + (uint32_t)((mt * 16 + aRow) * LDR + ks * 16 + aCol) * 2u;
                LDSM4(af[mt][0], af[mt][1], af[mt][2], af[mt][3], addr);
            }
#pragma unroll
            for (int p = 0; p < 2; p++) {
                uint32_t bf0, bf1, bf2, bf3;
                uint32_t addr = sb + (uint32_t)(OFF_X +
                    (n1base + p * 16 + bRow) * LDX + ks * 16 + bCol) * 2u;
                LDSM4(bf0, bf1, bf2, bf3, addr);
#pragma unroll
                for (int mt = 0; mt < 4; mt++) {
                    MMA16(z[mt][2 * p],     af[mt][0], af[mt][1], af[mt][2], af[mt][3], bf0, bf1);
                    MMA16(z[mt][2 * p + 1], af[mt][0], af[mt][1], af[mt][2], af[mt][3], bf2, bf3);
                }
            }
        }
        // store Zt shard (fp16)
#pragma unroll
        for (int mt = 0; mt < 4; mt++)
#pragma unroll
            for (int nt = 0; nt < 4; nt++) {
                int col = n1base + nt * 8 + t4 * 2;
                *reinterpret_cast<__half2*>(sZ + (mt * 16 + g) * LDZ + col) =
                    __floats2half2_rn(z[mt][nt][0], z[mt][nt][1]);
                *reinterpret_cast<__half2*>(sZ + (mt * 16 + g + 8) * LDZ + col) =
                    __floats2half2_rn(z[mt][nt][2], z[mt][nt][3]);
            }

        if (i < 14) CP_WAIT1(); else CP_WAIT0();   // F(i+1) complete
        __syncthreads();                           // publish Zt(i) and F(i+1)

        // ---- GEMM2: Y_bb[n12][n34] += L2_r2 . Zt_bb^T (M=64,N=32,K=64) ------
#pragma unroll
        for (int ks = 0; ks < 4; ks++) {
            uint32_t af[4][4];
#pragma unroll
            for (int mt = 0; mt < 4; mt++) {
                uint32_t addr = fL + (uint32_t)((mt * 16 + aRow) * LDR + ks * 16 + aCol) * 2u;
                LDSM4(af[mt][0], af[mt][1], af[mt][2], af[mt][3], addr);
            }
#pragma unroll
            for (int p = 0; p < 2; p++) {
                uint32_t bf0, bf1, bf2, bf3;
                uint32_t addr = sb + (uint32_t)(zOff +
                    (n2base + p * 16 + bRow) * LDZ + bb * 64 + ks * 16 + bCol) * 2u;
                LDSM4(bf0, bf1, bf2, bf3, addr);
#pragma unroll
                for (int mt = 0; mt < 4; mt++) {
                    MMA16(accY[mt][2 * p],     af[mt][0], af[mt][1], af[mt][2], af[mt][3], bf0, bf1);
                    MMA16(accY[mt][2 * p + 1], af[mt][0], af[mt][1], af[mt][2], af[mt][3], bf2, bf3);
                }
            }
        }
        // NOTE: no barrier here — GEMM1(i+1) writes the other Z buffer, and
        // factor slot (i+2)&3 was last read before the barrier above.
    }

    // ---- epilogue: Y + bias -> y[b0+bb][n12*64+n34] -------------------------
    float* yb = y + (size_t)(b0 + bb) * 4096;
#pragma unroll
    for (int mt = 0; mt < 4; mt++)
#pragma unroll
        for (int nt = 0; nt < 4; nt++) {
            int row = mt * 16 + g;
            int col = n2base + nt * 8 + t4 * 2;
            float2 bv0 = *reinterpret_cast<const float2*>(bias + row * 64 + col);
            float2 bv1 = *reinterpret_cast<const float2*>(bias + (row + 8) * 64 + col);
            float2 o0, o1;
            o0.x = accY[mt][nt][0] + bv0.x;  o0.y = accY[mt][nt][1] + bv0.y;
            o1.x = accY[mt][nt][2] + bv1.x;  o1.y = accY[mt][nt][3] + bv1.y;
            *reinterpret_cast<float2*>(yb + row * 64 + col) = o0;
            *reinterpret_cast<float2*>(yb + (row + 8) * 64 + col) = o1;
        }
}

// ---------------- launch -----------------------------------------------------
extern "C" void kernel_launch(void* const* d_in, const int* in_sizes, int n_in,
                              void* d_out, int out_size) {
    const float* x    = (const float*)d_in[0];
    const float* c0   = (const float*)d_in[1];
    const float* c1   = (const float*)d_in[2];
    const float* c2   = (const float*)d_in[3];
    const float* c3   = (const float*)d_in[4];
    const float* bias = (const float*)d_in[5];
    float* out = (float*)d_out;

    k_r2h<<<256, 256>>>(c2, c3);
    k_l2h<<<256, 256>>>(c0, c1);

    cudaFuncSetAttribute(tt_fused, cudaFuncAttributeMaxDynamicSharedMemorySize, SMEM_BYTES);
    tt_fused<<<2048, 256, SMEM_BYTES>>>(x, bias, out);
}

// round 5
// speedup vs baseline: 4.0428x; 1.0747x over previous
#include <cuda_runtime.h>
#include <cuda_fp16.h>
#include <cstdint>
#include <cstddef>

// ============================================================================
// TT linear layer, fused Kronecker-sandwich, register-resident Z:
//   Y_b = sum_{r2=0..15}  L2_r2 (64x64) . X_b (64x64) . R2_r2^T (64x64)
// CTA = 4 samples, 256 threads = 8 warps. Warp w: sample bb=w&3, n34-half w>>2.
//   GEMM1 (per r2): Zt[n34 32][m12 64] = R2_r2 . X_bb^T
//        A = R2 (LDSM from factor ring), B = X (REGISTER-RESIDENT, loaded once)
//   pack: Zt D-accum (f32) -> A-fragments (f16x2) in registers  [FA2 trick]
//   GEMM2 (per r2): Yt[n34 32][n12 64] += Zt . L2^T
//        A = Zt regs, B = L2 (LDSM from factor ring)
// No SMEM intermediate; one barrier per r2 (factor ring publish only).
// ============================================================================

__device__ __forceinline__ uint32_t smem_u32(const void* p) {
    uint32_t a;
    asm("{ .reg .u64 t; cvta.to.shared.u64 t, %1; cvt.u32.u64 %0, t; }" : "=r"(a) : "l"(p));
    return a;
}
__device__ __forceinline__ void cpa16(uint32_t d, const void* s) {
    asm volatile("cp.async.cg.shared.global [%0], [%1], 16;" :: "r"(d), "l"(s));
}
#define CP_COMMIT() asm volatile("cp.async.commit_group;" ::: "memory")
#define CP_WAIT1()  asm volatile("cp.async.wait_group 1;" ::: "memory")
#define CP_WAIT0()  asm volatile("cp.async.wait_group 0;" ::: "memory")

#define MMA16(d, a0, a1, a2, a3, b0, b1) asm volatile( \
    "mma.sync.aligned.m16n8k16.row.col.f32.f16.f16.f32 " \
    "{%0,%1,%2,%3},{%4,%5,%6,%7},{%8,%9},{%0,%1,%2,%3};" \
    : "+f"((d)[0]), "+f"((d)[1]), "+f"((d)[2]), "+f"((d)[3]) \
    : "r"(a0), "r"(a1), "r"(a2), "r"(a3), "r"(b0), "r"(b1))

#define LDSM4(r0, r1, r2_, r3, addr) asm volatile( \
    "ldmatrix.sync.aligned.m8n8.x4.shared.b16 {%0,%1,%2,%3}, [%4];" \
    : "=r"(r0), "=r"(r1), "=r"(r2_), "=r"(r3) : "r"(addr))

__device__ __forceinline__ uint32_t packh2(float lo, float hi) {
    uint32_t r;
    asm("cvt.rn.f16x2.f32 %0, %2, %1;" : "=r"(r) : "f"(lo), "f"(hi));
    return r;
}

// ---------------- layout constants (fp16 element units) --------------------
static constexpr int LDX = 72;    // X   [256][64]
static constexpr int LDR = 72;    // R/L [64][64]
static constexpr int OFF_X = 0;                          // 256*72 = 18432
static constexpr int OFF_F = 18432;
static constexpr int FBUF  = 2 * 64 * LDR;               // 9216 halves (R | L)
static constexpr int SMEM_HALFS = OFF_F + 4 * FBUF;      // 55296
static constexpr uint32_t SMEM_BYTES = SMEM_HALFS * 2;   // 110592

// ---------------- device-side factor slices --------------------------------
__device__ __half g_R2h[16 * 64 * 64];   // [r2][n34][m34]
__device__ __half g_L2h[16 * 64 * 64];   // [r2][n12][m12]

// ---------------- prep: both factor contractions in one kernel -------------
__global__ void k_prep(const float* __restrict__ c0, const float* __restrict__ c1,
                       const float* __restrict__ c2, const float* __restrict__ c3) {
    int t = blockIdx.x * 256 + threadIdx.x;      // 0..131071
    if (t < 65536) {
        int m34 = t & 63, n34 = (t >> 6) & 63, r2 = t >> 12;
        int m3 = m34 >> 3, m4 = m34 & 7, n3 = n34 >> 3, n4 = n34 & 7;
        float s = 0.f;
#pragma unroll
        for (int r3 = 0; r3 < 16; r3++)
            s += c2[((r2 * 8 + n3) * 8 + m3) * 16 + r3] * c3[(r3 * 8 + n4) * 8 + m4];
        g_R2h[t] = __float2half_rn(s);
    } else {
        int u = t - 65536;
        int m12 = u & 63, n12 = (u >> 6) & 63, r2 = u >> 12;
        int m1 = m12 >> 3, m2 = m12 & 7, n1 = n12 >> 3, n2 = n12 & 7;
        float s = 0.f;
#pragma unroll
        for (int r1 = 0; r1 < 16; r1++)
            s += c0[(n1 * 8 + m1) * 16 + r1] * c1[((r1 * 8 + n2) * 8 + m2) * 16 + r2];
        g_L2h[u] = __float2half_rn(s);
    }
}

// ---------------- factor prefetch: R2[r2] + L2[r2] -> ring slot -------------
__device__ __forceinline__ void prefetch_factors(uint32_t sb, int tid, int r2) {
    const uint32_t f0 = sb + (uint32_t)(OFF_F + (r2 & 3) * FBUF) * 2u;
    const __half* gR = g_R2h + r2 * 4096;
    const __half* gL = g_L2h + r2 * 4096;
#pragma unroll
    for (int k = 0; k < 2; k++) {
        int i = tid + k * 256;            // 0..511 16B chunks
        int row = i >> 3, c = i & 7;
        uint32_t d = (uint32_t)(row * LDR + c * 8) * 2u;
        cpa16(f0 + d, gR + row * 64 + c * 8);
        cpa16(f0 + (uint32_t)(64 * LDR) * 2u + d, gL + row * 64 + c * 8);
    }
    CP_COMMIT();
}

// ---------------- fused main kernel -----------------------------------------
__global__ void __launch_bounds__(256, 1)
tt_fused(const float* __restrict__ x, const float* __restrict__ bias,
         float* __restrict__ y) {
    extern __shared__ __half sm[];
    const uint32_t sb = smem_u32(sm);
    const int tid = threadIdx.x, wid = tid >> 5, lane = tid & 31;
    const int g = lane >> 2, t4 = lane & 3;
    const int b0 = blockIdx.x * 4;

    const int bb = wid & 3;           // warp's sample
    const int half34 = wid >> 2;      // warp's n34-half (rows half34*32..+31)

    // ldmatrix per-thread selectors (same as round 4)
    const int aRow = lane & 15,                      aCol = (lane >> 4) * 8;
    const int bRow = ((lane >> 4) * 8) + (lane & 7), bCol = ((lane >> 3) & 1) * 8;

    // ---- load X (4 samples x 4096 fp32) -> fp16 SMEM [(b,m12)][m34] --------
    {
        const float4* gx = reinterpret_cast<const float4*>(x + (size_t)b0 * 4096);
        __half* sX = sm + OFF_X;
#pragma unroll
        for (int j = 0; j < 16; j++) {
            int i = tid + j * 256;
            int row = i >> 4, c = i & 15;
            float4 v = gx[i];
            *reinterpret_cast<__half2*>(sX + row * LDX + c * 4)     = __floats2half2_rn(v.x, v.y);
            *reinterpret_cast<__half2*>(sX + row * LDX + c * 4 + 2) = __floats2half2_rn(v.z, v.w);
        }
    }
    prefetch_factors(sb, tid, 0);
    prefetch_factors(sb, tid, 1);
    CP_WAIT1();
    __syncthreads();           // X + F(0) published

    // ---- X B-fragments, register-resident for all 16 r2 --------------------
    // GEMM1: B[n=m12][k=m34]; warp's rows = bb*64 + m12. xB[ks][p][0..3]:
    // (0,1) = n8 tile 2p frag, (2,3) = n8 tile 2p+1 frag (k16 = ks).
    uint32_t xB[4][4][4];
#pragma unroll
    for (int ks = 0; ks < 4; ks++)
#pragma unroll
        for (int p = 0; p < 4; p++) {
            uint32_t addr = sb + (uint32_t)(OFF_X +
                (bb * 64 + p * 16 + bRow) * LDX + ks * 16 + bCol) * 2u;
            LDSM4(xB[ks][p][0], xB[ks][p][1], xB[ks][p][2], xB[ks][p][3], addr);
        }

    float accY[2][8][4];
#pragma unroll
    for (int a = 0; a < 2; a++)
#pragma unroll
        for (int b = 0; b < 8; b++)
#pragma unroll
            for (int d = 0; d < 4; d++) accY[a][b][d] = 0.f;

#pragma unroll 1
    for (int i = 0; i < 16; i++) {
        if (i + 2 < 16) prefetch_factors(sb, tid, i + 2);

        const uint32_t fR = sb + (uint32_t)(OFF_F + (i & 3) * FBUF) * 2u;
        const uint32_t fL = fR + (uint32_t)(64 * LDR) * 2u;

        // ---- GEMM1: Zt[n34 32][m12 64] = R2_r2 . X^T  (reg accum) ----------
        float z[2][8][4];
#pragma unroll
        for (int a = 0; a < 2; a++)
#pragma unroll
            for (int b = 0; b < 8; b++)
#pragma unroll
                for (int d = 0; d < 4; d++) z[a][b][d] = 0.f;

#pragma unroll
        for (int ks = 0; ks < 4; ks++) {
            uint32_t af[2][4];
#pragma unroll
            for (int mt = 0; mt < 2; mt++) {
                uint32_t addr = fR + (uint32_t)((half34 * 32 + mt * 16 + aRow) * LDR
                                                + ks * 16 + aCol) * 2u;
                LDSM4(af[mt][0], af[mt][1], af[mt][2], af[mt][3], addr);
            }
#pragma unroll
            for (int p = 0; p < 4; p++)
#pragma unroll
                for (int mt = 0; mt < 2; mt++) {
                    MMA16(z[mt][2 * p],     af[mt][0], af[mt][1], af[mt][2], af[mt][3],
                          xB[ks][p][0], xB[ks][p][1]);
                    MMA16(z[mt][2 * p + 1], af[mt][0], af[mt][1], af[mt][2], af[mt][3],
                          xB[ks][p][2], xB[ks][p][3]);
                }
        }

        // ---- pack Zt f32 accum -> f16x2 A-fragments (no SMEM!) -------------
        // A-frag k16 group j comes from D n8-tiles {2j, 2j+1}.
        uint32_t zA[2][4][4];
#pragma unroll
        for (int mt = 0; mt < 2; mt++)
#pragma unroll
            for (int j = 0; j < 4; j++) {
                zA[mt][j][0] = packh2(z[mt][2 * j][0],     z[mt][2 * j][1]);
                zA[mt][j][1] = packh2(z[mt][2 * j][2],     z[mt][2 * j][3]);
                zA[mt][j][2] = packh2(z[mt][2 * j + 1][0], z[mt][2 * j + 1][1]);
                zA[mt][j][3] = packh2(z[mt][2 * j + 1][2], z[mt][2 * j + 1][3]);
            }

        // ---- GEMM2: Yt[n34 32][n12 64] += Zt . L2^T  -----------------------
#pragma unroll
        for (int ks = 0; ks < 4; ks++) {
            uint32_t lB[4][4];
#pragma unroll
            for (int q = 0; q < 4; q++) {
                uint32_t addr = fL + (uint32_t)((q * 16 + bRow) * LDR
                                                + ks * 16 + bCol) * 2u;
                LDSM4(lB[q][0], lB[q][1], lB[q][2], lB[q][3], addr);
            }
#pragma unroll
            for (int q = 0; q < 4; q++)
#pragma unroll
                for (int mt = 0; mt < 2; mt++) {
                    MMA16(accY[mt][2 * q],     zA[mt][ks][0], zA[mt][ks][1],
                          zA[mt][ks][2], zA[mt][ks][3], lB[q][0], lB[q][1]);
                    MMA16(accY[mt][2 * q + 1], zA[mt][ks][0], zA[mt][ks][1],
                          zA[mt][ks][2], zA[mt][ks][3], lB[q][2], lB[q][3]);
                }
        }

        // publish F(i+1); also fences factor-slot reuse two iterations out
        if (i < 15) {
            if (i < 14) CP_WAIT1(); else CP_WAIT0();
            __syncthreads();
        }
    }

    // ---- epilogue: y[b0+bb][n12*64 + n34] = Yt + bias -----------------------
    // accY[mt][n8]: rows n34 = half34*32 + mt*16 + g(+8), cols n12 = n8*8 + 2*t4(+1)
    float* yb = y + (size_t)(b0 + bb) * 4096;
#pragma unroll
    for (int mt = 0; mt < 2; mt++) {
        const int n34r = half34 * 32 + mt * 16 + g;
#pragma unroll
        for (int n8 = 0; n8 < 8; n8++) {
            const int n12c = n8 * 8 + t4 * 2;
            const int e00 = n12c * 64 + n34r;          // (n12c  , n34r  )
            const int e10 = e00 + 64;                  // (n12c+1, n34r  )
            yb[e00]     = accY[mt][n8][0] + __ldg(bias + e00);
            yb[e10]     = accY[mt][n8][1] + __ldg(bias + e10);
            yb[e00 + 8] = accY[mt][n8][2] + __ldg(bias + e00 + 8);
            yb[e10 + 8] = accY[mt][n8][3] + __ldg(bias + e10 + 8);
        }
    }
}

// ---------------- launch -----------------------------------------------------
extern "C" void kernel_launch(void* const* d_in, const int* in_sizes, int n_in,
                              void* d_out, int out_size) {
    const float* x    = (const float*)d_in[0];
    const float* c0   = (const float*)d_in[1];
    const float* c1   = (const float*)d_in[2];
    const float* c2   = (const float*)d_in[3];
    const float* c3   = (const float*)d_in[4];
    const float* bias = (const float*)d_in[5];
    float* out = (float*)d_out;

    k_prep<<<512, 256>>>(c0, c1, c2, c3);

    cudaFuncSetAttribute(tt_fused, cudaFuncAttributeMaxDynamicSharedMemorySize, SMEM_BYTES);
    tt_fused<<<2048, 256, SMEM_BYTES>>>(x, bias, out);
}

// round 6
// speedup vs baseline: 4.2696x; 1.0561x over previous
#include <cuda_runtime.h>
#include <cuda_fp16.h>
#include <cstdint>
#include <cstddef>

// ============================================================================
// TT linear layer, fused Kronecker-sandwich, register-resident Z:
//   Y_b = sum_{r2=0..15}  L2_r2 (64x64) . X_b (64x64) . R2_r2^T (64x64)
// CTA = 4 samples, 256 threads = 8 warps. Warp w: sample bb=w&3, n34-half w>>2.
//   GEMM1 (per r2): Zt[n34 32][m12 64] = R2_r2 . X_bb^T   (X register-resident)
//   pack: Zt f32 accum -> f16x2 A-fragments (registers, FA2 trick)
//   GEMM2 (per r2): Yt[n34 32][n12 64] += Zt . L2^T
// Round 6: 8-slot factor ring, prefetch distance 4, __syncthreads only every
// 4 iterations -> warps on the same SMSP de-phase and cover each other's
// pack/LDSM bubbles. 4 CTA barriers total (was 16).
// ============================================================================

__device__ __forceinline__ uint32_t smem_u32(const void* p) {
    uint32_t a;
    asm("{ .reg .u64 t; cvta.to.shared.u64 t, %1; cvt.u32.u64 %0, t; }" : "=r"(a) : "l"(p));
    return a;
}
__device__ __forceinline__ void cpa16(uint32_t d, const void* s) {
    asm volatile("cp.async.cg.shared.global [%0], [%1], 16;" :: "r"(d), "l"(s));
}
#define CP_COMMIT() asm volatile("cp.async.commit_group;" ::: "memory")
#define CP_WAIT0()  asm volatile("cp.async.wait_group 0;" ::: "memory")

#define MMA16(d, a0, a1, a2, a3, b0, b1) asm volatile( \
    "mma.sync.aligned.m16n8k16.row.col.f32.f16.f16.f32 " \
    "{%0,%1,%2,%3},{%4,%5,%6,%7},{%8,%9},{%0,%1,%2,%3};" \
    : "+f"((d)[0]), "+f"((d)[1]), "+f"((d)[2]), "+f"((d)[3]) \
    : "r"(a0), "r"(a1), "r"(a2), "r"(a3), "r"(b0), "r"(b1))

#define LDSM4(r0, r1, r2_, r3, addr) asm volatile( \
    "ldmatrix.sync.aligned.m8n8.x4.shared.b16 {%0,%1,%2,%3}, [%4];" \
    : "=r"(r0), "=r"(r1), "=r"(r2_), "=r"(r3) : "r"(addr))

__device__ __forceinline__ uint32_t packh2(float lo, float hi) {
    uint32_t r;
    asm("cvt.rn.f16x2.f32 %0, %2, %1;" : "=r"(r) : "f"(lo), "f"(hi));
    return r;
}

// ---------------- layout constants (fp16 element units) --------------------
static constexpr int LDX = 72;    // X   [256][64]   (144B rows, LDSM-safe)
static constexpr int LDR = 72;    // R/L [64][64]
static constexpr int OFF_X = 0;                          // 256*72 = 18432
static constexpr int OFF_F = 18432;
static constexpr int FBUF  = 2 * 64 * LDR;               // 9216 halves (R | L)
static constexpr int NSLOT = 8;                          // factor ring depth
static constexpr int SMEM_HALFS = OFF_F + NSLOT * FBUF;  // 92160
static constexpr uint32_t SMEM_BYTES = SMEM_HALFS * 2;   // 184320

// ---------------- device-side factor slices --------------------------------
__device__ __half g_R2h[16 * 64 * 64];   // [r2][n34][m34]
__device__ __half g_L2h[16 * 64 * 64];   // [r2][n12][m12]

// ---------------- prep: both factor contractions in one kernel -------------
__global__ void k_prep(const float* __restrict__ c0, const float* __restrict__ c1,
                       const float* __restrict__ c2, const float* __restrict__ c3) {
    int t = blockIdx.x * 256 + threadIdx.x;      // 0..131071
    if (t < 65536) {
        int m34 = t & 63, n34 = (t >> 6) & 63, r2 = t >> 12;
        int m3 = m34 >> 3, m4 = m34 & 7, n3 = n34 >> 3, n4 = n34 & 7;
        float s = 0.f;
#pragma unroll
        for (int r3 = 0; r3 < 16; r3++)
            s += c2[((r2 * 8 + n3) * 8 + m3) * 16 + r3] * c3[(r3 * 8 + n4) * 8 + m4];
        g_R2h[t] = __float2half_rn(s);
    } else {
        int u = t - 65536;
        int m12 = u & 63, n12 = (u >> 6) & 63, r2 = u >> 12;
        int m1 = m12 >> 3, m2 = m12 & 7, n1 = n12 >> 3, n2 = n12 & 7;
        float s = 0.f;
#pragma unroll
        for (int r1 = 0; r1 < 16; r1++)
            s += c0[(n1 * 8 + m1) * 16 + r1] * c1[((r1 * 8 + n2) * 8 + m2) * 16 + r2];
        g_L2h[u] = __float2half_rn(s);
    }
}

// ---------------- factor prefetch: R2[r2] + L2[r2] -> ring slot r2&7 --------
__device__ __forceinline__ void prefetch_factors(uint32_t sb, int tid, int r2) {
    const uint32_t f0 = sb + (uint32_t)(OFF_F + (r2 & (NSLOT - 1)) * FBUF) * 2u;
    const __half* gR = g_R2h + r2 * 4096;
    const __half* gL = g_L2h + r2 * 4096;
#pragma unroll
    for (int k = 0; k < 2; k++) {
        int i = tid + k * 256;            // 0..511 16B chunks
        int row = i >> 3, c = i & 7;
        uint32_t d = (uint32_t)(row * LDR + c * 8) * 2u;
        cpa16(f0 + d, gR + row * 64 + c * 8);
        cpa16(f0 + (uint32_t)(64 * LDR) * 2u + d, gL + row * 64 + c * 8);
    }
    CP_COMMIT();
}

// ---------------- fused main kernel -----------------------------------------
__global__ void __launch_bounds__(256, 1)
tt_fused(const float* __restrict__ x, const float* __restrict__ bias,
         float* __restrict__ y) {
    extern __shared__ __half sm[];
    const uint32_t sb = smem_u32(sm);
    const int tid = threadIdx.x, wid = tid >> 5, lane = tid & 31;
    const int g = lane >> 2, t4 = lane & 3;
    const int b0 = blockIdx.x * 4;

    const int bb = wid & 3;           // warp's sample
    const int half34 = wid >> 2;      // warp's n34-half (rows half34*32..+31)

    // ldmatrix per-thread selectors
    const int aRow = lane & 15,                      aCol = (lane >> 4) * 8;
    const int bRow = ((lane >> 4) * 8) + (lane & 7), bCol = ((lane >> 3) & 1) * 8;

    // ---- load X (4 samples x 4096 fp32) -> fp16 SMEM [(b,m12)][m34] --------
    {
        const float4* gx = reinterpret_cast<const float4*>(x + (size_t)b0 * 4096);
        __half* sX = sm + OFF_X;
#pragma unroll
        for (int j = 0; j < 16; j++) {
            int i = tid + j * 256;
            int row = i >> 4, c = i & 15;
            float4 v = gx[i];
            *reinterpret_cast<__half2*>(sX + row * LDX + c * 4)     = __floats2half2_rn(v.x, v.y);
            *reinterpret_cast<__half2*>(sX + row * LDX + c * 4 + 2) = __floats2half2_rn(v.z, v.w);
        }
    }
    // prologue: fill first 4 ring slots
    prefetch_factors(sb, tid, 0);
    prefetch_factors(sb, tid, 1);
    prefetch_factors(sb, tid, 2);
    prefetch_factors(sb, tid, 3);
    CP_WAIT0();
    __syncthreads();           // X + F(0..3) published

    // ---- X B-fragments, register-resident for all 16 r2 --------------------
    uint32_t xB[4][4][4];
#pragma unroll
    for (int ks = 0; ks < 4; ks++)
#pragma unroll
        for (int p = 0; p < 4; p++) {
            uint32_t addr = sb + (uint32_t)(OFF_X +
                (bb * 64 + p * 16 + bRow) * LDX + ks * 16 + bCol) * 2u;
            LDSM4(xB[ks][p][0], xB[ks][p][1], xB[ks][p][2], xB[ks][p][3], addr);
        }

    float accY[2][8][4];
#pragma unroll
    for (int a = 0; a < 2; a++)
#pragma unroll
        for (int b = 0; b < 8; b++)
#pragma unroll
            for (int d = 0; d < 4; d++) accY[a][b][d] = 0.f;

#pragma unroll 1
    for (int i = 0; i < 16; i++) {
        // window boundary: publish slots prefetched during previous window
        if (i && (i & 3) == 0) {
            CP_WAIT0();
            __syncthreads();
        }
        // prefetch 4 ahead into 8-slot ring (drift-safe, see header comment)
        if (i + 4 < 16) prefetch_factors(sb, tid, i + 4);

        const uint32_t fR = sb + (uint32_t)(OFF_F + (i & (NSLOT - 1)) * FBUF) * 2u;
        const uint32_t fL = fR + (uint32_t)(64 * LDR) * 2u;

        // ---- GEMM1: Zt[n34 32][m12 64] = R2_r2 . X^T  (reg accum) ----------
        float z[2][8][4];
#pragma unroll
        for (int a = 0; a < 2; a++)
#pragma unroll
            for (int b = 0; b < 8; b++)
#pragma unroll
                for (int d = 0; d < 4; d++) z[a][b][d] = 0.f;

#pragma unroll
        for (int ks = 0; ks < 4; ks++) {
            uint32_t af[2][4];
#pragma unroll
            for (int mt = 0; mt < 2; mt++) {
                uint32_t addr = fR + (uint32_t)((half34 * 32 + mt * 16 + aRow) * LDR
                                                + ks * 16 + aCol) * 2u;
                LDSM4(af[mt][0], af[mt][1], af[mt][2], af[mt][3], addr);
            }
#pragma unroll
            for (int p = 0; p < 4; p++)
#pragma unroll
                for (int mt = 0; mt < 2; mt++) {
                    MMA16(z[mt][2 * p],     af[mt][0], af[mt][1], af[mt][2], af[mt][3],
                          xB[ks][p][0], xB[ks][p][1]);
                    MMA16(z[mt][2 * p + 1], af[mt][0], af[mt][1], af[mt][2], af[mt][3],
                          xB[ks][p][2], xB[ks][p][3]);
                }
        }

        // ---- pack Zt f32 accum -> f16x2 A-fragments (registers) ------------
        uint32_t zA[2][4][4];
#pragma unroll
        for (int mt = 0; mt < 2; mt++)
#pragma unroll
            for (int j = 0; j < 4; j++) {
                zA[mt][j][0] = packh2(z[mt][2 * j][0],     z[mt][2 * j][1]);
                zA[mt][j][1] = packh2(z[mt][2 * j][2],     z[mt][2 * j][3]);
                zA[mt][j][2] = packh2(z[mt][2 * j + 1][0], z[mt][2 * j + 1][1]);
                zA[mt][j][3] = packh2(z[mt][2 * j + 1][2], z[mt][2 * j + 1][3]);
            }

        // ---- GEMM2: Yt[n34 32][n12 64] += Zt . L2^T  -----------------------
#pragma unroll
        for (int ks = 0; ks < 4; ks++) {
            uint32_t lB[4][4];
#pragma unroll
            for (int q = 0; q < 4; q++) {
                uint32_t addr = fL + (uint32_t)((q * 16 + bRow) * LDR
                                                + ks * 16 + bCol) * 2u;
                LDSM4(lB[q][0], lB[q][1], lB[q][2], lB[q][3], addr);
            }
#pragma unroll
            for (int q = 0; q < 4; q++)
#pragma unroll
                for (int mt = 0; mt < 2; mt++) {
                    MMA16(accY[mt][2 * q],     zA[mt][ks][0], zA[mt][ks][1],
                          zA[mt][ks][2], zA[mt][ks][3], lB[q][0], lB[q][1]);
                    MMA16(accY[mt][2 * q + 1], zA[mt][ks][0], zA[mt][ks][1],
                          zA[mt][ks][2], zA[mt][ks][3], lB[q][2], lB[q][3]);
                }
        }
    }

    // ---- epilogue: y[b0+bb][n12*64 + n34] = Yt + bias -----------------------
    float* yb = y + (size_t)(b0 + bb) * 4096;
#pragma unroll
    for (int mt = 0; mt < 2; mt++) {
        const int n34r = half34 * 32 + mt * 16 + g;
#pragma unroll
        for (int n8 = 0; n8 < 8; n8++) {
            const int n12c = n8 * 8 + t4 * 2;
            const int e00 = n12c * 64 + n34r;          // (n12c  , n34r  )
            const int e10 = e00 + 64;                  // (n12c+1, n34r  )
            yb[e00]     = accY[mt][n8][0] + __ldg(bias + e00);
            yb[e10]     = accY[mt][n8][1] + __ldg(bias + e10);
            yb[e00 + 8] = accY[mt][n8][2] + __ldg(bias + e00 + 8);
            yb[e10 + 8] = accY[mt][n8][3] + __ldg(bias + e10 + 8);
        }
    }
}

// ---------------- launch -----------------------------------------------------
extern "C" void kernel_launch(void* const* d_in, const int* in_sizes, int n_in,
                              void* d_out, int out_size) {
    const float* x    = (const float*)d_in[0];
    const float* c0   = (const float*)d_in[1];
    const float* c1   = (const float*)d_in[2];
    const float* c2   = (const float*)d_in[3];
    const float* c3   = (const float*)d_in[4];
    const float* bias = (const float*)d_in[5];
    float* out = (float*)d_out;

    k_prep<<<512, 256>>>(c0, c1, c2, c3);

    cudaFuncSetAttribute(tt_fused, cudaFuncAttributeMaxDynamicSharedMemorySize, SMEM_BYTES);
    tt_fused<<<2048, 256, SMEM_BYTES>>>(x, bias, out);
}